// round 14
// baseline (speedup 1.0000x reference)
#include <cuda_runtime.h>
#include <math.h>

#define Bn 16
#define Cn 128
#define Ln 2048

__device__ float g_inv[Bn * Ln];   // per-query 1/rowsum, K1 -> K2

__device__ __forceinline__ unsigned f2tf32(float x) {
    unsigned r;
    asm("cvt.rna.tf32.f32 %0, %1;" : "=r"(r) : "f"(x));
    return r;
}

__device__ __forceinline__ void mma_tf32(float* c, const unsigned* a, const unsigned* b) {
    asm volatile(
        "mma.sync.aligned.m16n8k8.row.col.f32.tf32.tf32.f32 "
        "{%0,%1,%2,%3}, {%4,%5,%6,%7}, {%8,%9}, {%0,%1,%2,%3};"
        : "+f"(c[0]), "+f"(c[1]), "+f"(c[2]), "+f"(c[3])
        : "r"(a[0]), "r"(a[1]), "r"(a[2]), "r"(a[3]), "r"(b[0]), "r"(b[1]));
}

// ---------------------------------------------------------------------------
// K1: per (b, q-strip 128): loop 32 k-tiles of 64.
//   QK tf32 mma -> p = exp(scale*e + log(mask+1e-6)) -> write unnormalized p
//   to attT[b][k][q]; block-local row sums -> g_inv.
// 256 threads = 8 warps, warp grid 2(m=k) x 4(n=q), warp tile 32x32.
// smem: Qs[128][136] + Ks[128][72] + sred[256] = 107,520 B -> 2 CTAs/SM.
// ---------------------------------------------------------------------------
__global__ void __launch_bounds__(256, 2)
qk_exp_kernel(const float* __restrict__ Q, const float* __restrict__ Kg,
              const float* __restrict__ mask, float* __restrict__ attT) {
    extern __shared__ float sm[];
    float* Qs   = sm;               // [128 c][136]  tf32 Q tile (persistent)
    float* Ks   = sm + 17408;       // [128 c][72]   tf32 K tile
    float* sred = sm + 26624;       // [256]

    const int b   = blockIdx.y;
    const int q0  = blockIdx.x * 128;
    const int tid = threadIdx.x;
    const int warp = tid >> 5, lane = tid & 31;
    const int wm = warp >> 2, wn = warp & 3;    // 2(m) x 4(n)
    const int g = lane >> 2, tg = lane & 3;

    const float* Qb   = Q  + (size_t)b * Cn * Ln;
    const float* Kb   = Kg + (size_t)b * Cn * Ln;
    const float* mrow = mask + b * Ln;
    float* Tb = attT + (size_t)b * Ln * Ln;

    sred[tid] = 0.f;

    // stage Q tile [c=128][q=128], tf32-rounded
#pragma unroll
    for (int i = 0; i < 16; i++) {
        int id = tid + i * 256;
        int r = id >> 5, c4 = (id & 31) << 2;
        float4 v = *reinterpret_cast<const float4*>(Qb + (size_t)r * Ln + q0 + c4);
        unsigned* d = reinterpret_cast<unsigned*>(Qs + r * 136 + c4);
        d[0] = f2tf32(v.x); d[1] = f2tf32(v.y); d[2] = f2tf32(v.z); d[3] = f2tf32(v.w);
    }

    // prefetch K tile 0 ([c=128][k=64])
    float4 pf[8];
#pragma unroll
    for (int i = 0; i < 8; i++) {
        int id = tid + i * 256;
        pf[i] = *reinterpret_cast<const float4*>(Kb + (size_t)(id >> 4) * Ln + ((id & 15) << 2));
    }
    __syncthreads();

    const float scale = 0.08838834764831845f;   // 1/sqrt(128)

    for (int kt = 0; kt < 32; kt++) {
        const int k0 = kt * 64;

        // commit prefetched K tile (convert to tf32)
#pragma unroll
        for (int i = 0; i < 8; i++) {
            int id = tid + i * 256;
            unsigned* d = reinterpret_cast<unsigned*>(Ks + (id >> 4) * 72 + ((id & 15) << 2));
            d[0] = f2tf32(pf[i].x); d[1] = f2tf32(pf[i].y);
            d[2] = f2tf32(pf[i].z); d[3] = f2tf32(pf[i].w);
        }
        __syncthreads();

        // prefetch next K tile (overlaps mma)
        {
            int kn = ((kt + 1) & 31) * 64;
#pragma unroll
            for (int i = 0; i < 8; i++) {
                int id = tid + i * 256;
                pf[i] = *reinterpret_cast<const float4*>(
                    Kb + (size_t)(id >> 4) * Ln + kn + ((id & 15) << 2));
            }
        }

        // QK mma: acc[m=k 32][n=q 32]
        float acc[2][4][4];
#pragma unroll
        for (int i = 0; i < 2; i++)
#pragma unroll
            for (int j = 0; j < 4; j++)
#pragma unroll
                for (int v = 0; v < 4; v++) acc[i][j][v] = 0.f;

#pragma unroll
        for (int cc = 0; cc < Cn; cc += 8) {
            unsigned a[2][4];
#pragma unroll
            for (int mt = 0; mt < 2; mt++) {
                int m = wm * 32 + mt * 16 + g;
                a[mt][0] = __float_as_uint(Ks[(cc + tg) * 72 + m]);
                a[mt][1] = __float_as_uint(Ks[(cc + tg) * 72 + m + 8]);
                a[mt][2] = __float_as_uint(Ks[(cc + tg + 4) * 72 + m]);
                a[mt][3] = __float_as_uint(Ks[(cc + tg + 4) * 72 + m + 8]);
            }
#pragma unroll
            for (int nt = 0; nt < 4; nt++) {
                int n = wn * 32 + nt * 8 + g;
                unsigned bb[2];
                bb[0] = __float_as_uint(Qs[(cc + tg) * 136 + n]);
                bb[1] = __float_as_uint(Qs[(cc + tg + 4) * 136 + n]);
                mma_tf32(acc[0][nt], a[0], bb);
                mma_tf32(acc[1][nt], a[1], bb);
            }
        }

        // epilogue: exp, streaming store, row-sum accumulation
        float sp[8];
#pragma unroll
        for (int j = 0; j < 8; j++) sp[j] = 0.f;
#pragma unroll
        for (int mt = 0; mt < 2; mt++) {
            int kgl = k0 + wm * 32 + mt * 16 + g;
            float l0 = __logf(__ldg(mrow + kgl) + 1e-6f);
            float l1 = __logf(__ldg(mrow + kgl + 8) + 1e-6f);
            float* row0 = Tb + (size_t)kgl * Ln + q0 + wn * 32;
            float* row1 = row0 + (size_t)8 * Ln;
#pragma unroll
            for (int nt = 0; nt < 4; nt++) {
                int qoff = nt * 8 + 2 * tg;
                float p0 = __expf(fmaf(acc[mt][nt][0], scale, l0));
                float p1 = __expf(fmaf(acc[mt][nt][1], scale, l0));
                float p2 = __expf(fmaf(acc[mt][nt][2], scale, l1));
                float p3 = __expf(fmaf(acc[mt][nt][3], scale, l1));
                sp[nt * 2]     += p0 + p2;
                sp[nt * 2 + 1] += p1 + p3;
                __stcs(reinterpret_cast<float2*>(row0 + qoff), make_float2(p0, p1));
                __stcs(reinterpret_cast<float2*>(row1 + qoff), make_float2(p2, p3));
            }
        }
#pragma unroll
        for (int j = 0; j < 8; j++) {
            float v = sp[j];
            v += __shfl_xor_sync(0xffffffffu, v, 4);
            v += __shfl_xor_sync(0xffffffffu, v, 8);
            v += __shfl_xor_sync(0xffffffffu, v, 16);
            if (g == 0)
                sred[wm * 128 + wn * 32 + (j >> 1) * 8 + 2 * tg + (j & 1)] += v;
        }
        __syncthreads();
    }

    if (tid < 128)
        g_inv[b * Ln + q0 + tid] = 1.0f / (sred[tid] + sred[128 + tid]);
}

// ---------------------------------------------------------------------------
// K2: per (b, q-strip 128): loop 64 k-tiles of 32.
//   read unnormalized p, scale by inv[q]*mask[k], write final attT,
//   AND accumulate out[c][q] += V * p_norm via tf32 mma.
// V tiles double-buffered with cp.async (raw fp32, tf32-rounded at frag load).
// 256 threads = 8 warps, warp grid 4(m=c) x 2(n=q), warp tile 32x64.
// smem: Ps[32][136] + Vs[2][128][36] + mrow[2048] + sinv[128] = 62,976 B.
// ---------------------------------------------------------------------------
__global__ void __launch_bounds__(256, 2)
norm_av_kernel(const float* __restrict__ V, const float* __restrict__ mask,
               float* __restrict__ attT, float* __restrict__ out) {
    extern __shared__ float sm2[];
    float* Ps   = sm2;              // [32 k][136]  tf32 normalized p tile
    float* Vs   = sm2 + 4352;       // [2][128 c][36] raw V tiles
    float* mrow = sm2 + 13568;      // [2048]
    float* sinv = sm2 + 15616;      // [128]

    const int b   = blockIdx.y;
    const int q0  = blockIdx.x * 128;
    const int tid = threadIdx.x;
    const int warp = tid >> 5, lane = tid & 31;
    const int wm = warp >> 1, wn = warp & 1;    // 4(m) x 2(n)
    const int g = lane >> 2, tg = lane & 3;

    const float* Vb = V + (size_t)b * Cn * Ln;
    float* Tb = attT + (size_t)b * Ln * Ln;

#pragma unroll
    for (int i = 0; i < 8; i++) mrow[tid + i * 256] = mask[b * Ln + tid + i * 256];
    if (tid < 128) sinv[tid] = g_inv[b * Ln + q0 + tid];

    // cp.async V tile 0 into buffer 0
#pragma unroll
    for (int i = 0; i < 4; i++) {
        int id = tid + i * 256;
        int r = id >> 3, ch = (id & 7) << 2;
        unsigned dst = (unsigned)__cvta_generic_to_shared(Vs + r * 36 + ch);
        asm volatile("cp.async.cg.shared.global [%0], [%1], 16;"
                     :: "r"(dst), "l"(Vb + (size_t)r * Ln + ch));
    }
    asm volatile("cp.async.commit_group;");
    __syncthreads();

    float oacc[2][8][4];
#pragma unroll
    for (int i = 0; i < 2; i++)
#pragma unroll
        for (int j = 0; j < 8; j++)
#pragma unroll
            for (int v = 0; v < 4; v++) oacc[i][j][v] = 0.f;

    for (int kt = 0; kt < 64; kt++) {
        const int k0 = kt * 32;

        // issue cp.async for V tile kt+1 (other buffer)
        {
            int kn = ((kt + 1) & 63) * 32;
            float* vdst = Vs + ((kt + 1) & 1) * 4608;
#pragma unroll
            for (int i = 0; i < 4; i++) {
                int id = tid + i * 256;
                int r = id >> 3, ch = (id & 7) << 2;
                unsigned dst = (unsigned)__cvta_generic_to_shared(vdst + r * 36 + ch);
                asm volatile("cp.async.cg.shared.global [%0], [%1], 16;"
                             :: "r"(dst), "l"(Vb + (size_t)r * Ln + kn + ch));
            }
            asm volatile("cp.async.commit_group;");
        }

        // p tile: load, normalize+mask, write final attT, stash tf32 in Ps
#pragma unroll
        for (int i = 0; i < 4; i++) {
            int id = tid + i * 256;
            int r = id >> 5, c4 = (id & 31) << 2;
            int kgl = k0 + r;
            float mk = mrow[kgl];
            float* gp = Tb + (size_t)kgl * Ln + q0 + c4;
            float4 v = __ldcs(reinterpret_cast<const float4*>(gp));
            float4 iv = *reinterpret_cast<const float4*>(sinv + c4);
            v.x *= iv.x * mk; v.y *= iv.y * mk;
            v.z *= iv.z * mk; v.w *= iv.w * mk;
            __stcs(reinterpret_cast<float4*>(gp), v);
            unsigned* d = reinterpret_cast<unsigned*>(Ps + r * 136 + c4);
            d[0] = f2tf32(v.x); d[1] = f2tf32(v.y);
            d[2] = f2tf32(v.z); d[3] = f2tf32(v.w);
        }
        asm volatile("cp.async.wait_group 1;");
        __syncthreads();

        // AV mma: oacc[m=c 32][n=q 64] += V * Pnorm
        const float* Vt = Vs + (kt & 1) * 4608;
#pragma unroll
        for (int kk = 0; kk < 32; kk += 8) {
            unsigned a[2][4];
#pragma unroll
            for (int mt = 0; mt < 2; mt++) {
                int m = wm * 32 + mt * 16 + g;
                a[mt][0] = f2tf32(Vt[m * 36 + kk + tg]);
                a[mt][1] = f2tf32(Vt[(m + 8) * 36 + kk + tg]);
                a[mt][2] = f2tf32(Vt[m * 36 + kk + tg + 4]);
                a[mt][3] = f2tf32(Vt[(m + 8) * 36 + kk + tg + 4]);
            }
#pragma unroll
            for (int nt = 0; nt < 8; nt++) {
                int n = wn * 64 + nt * 8 + g;
                unsigned bb[2];
                bb[0] = __float_as_uint(Ps[(kk + tg) * 136 + n]);
                bb[1] = __float_as_uint(Ps[(kk + tg + 4) * 136 + n]);
                mma_tf32(oacc[0][nt], a[0], bb);
                mma_tf32(oacc[1][nt], a[1], bb);
            }
        }
        __syncthreads();
    }

    // out[b][c][q] (already normalized & masked)
    float* ob = out + (size_t)b * Cn * Ln;
#pragma unroll
    for (int mt = 0; mt < 2; mt++) {
        int c = wm * 32 + mt * 16 + g;
#pragma unroll
        for (int nt = 0; nt < 8; nt++) {
            int q = q0 + wn * 64 + nt * 8 + 2 * tg;
            __stcs(reinterpret_cast<float2*>(ob + (size_t)c * Ln + q),
                   make_float2(oacc[mt][nt][0], oacc[mt][nt][1]));
            __stcs(reinterpret_cast<float2*>(ob + (size_t)(c + 8) * Ln + q),
                   make_float2(oacc[mt][nt][2], oacc[mt][nt][3]));
        }
    }
}

// ---------------------------------------------------------------------------
extern "C" void kernel_launch(void* const* d_in, const int* in_sizes, int n_in,
                              void* d_out, int out_size) {
    const float* Q    = (const float*)d_in[0];
    const float* K    = (const float*)d_in[1];
    const float* V    = (const float*)d_in[2];
    const float* mask = (const float*)d_in[3];

    float* out  = (float*)d_out;                  // [B, C, L]
    float* attT = out + (size_t)Bn * Cn * Ln;     // [B, Lk, Lq]

    const int SMEM1 = 26880 * 4;                  // 107,520 B
    const int SMEM2 = 15744 * 4;                  //  62,976 B
    cudaFuncSetAttribute(qk_exp_kernel,
                         cudaFuncAttributeMaxDynamicSharedMemorySize, SMEM1);
    cudaFuncSetAttribute(norm_av_kernel,
                         cudaFuncAttributeMaxDynamicSharedMemorySize, SMEM2);

    dim3 grid(Ln / 128, Bn);                      // (16, 16) = 256 blocks
    qk_exp_kernel<<<grid, 256, SMEM1>>>(Q, K, mask, attT);
    norm_av_kernel<<<grid, 256, SMEM2>>>(V, mask, attT, out);
}

// round 15
// speedup vs baseline: 1.0021x; 1.0021x over previous
#include <cuda_runtime.h>
#include <math.h>

#define Bn 16
#define Cn 128
#define Ln 2048

__device__ float g_inv[Bn * Ln];   // per-query 1/rowsum, K1 -> K2

__device__ __forceinline__ unsigned f2tf32(float x) {
    unsigned r;
    asm("cvt.rna.tf32.f32 %0, %1;" : "=r"(r) : "f"(x));
    return r;
}

__device__ __forceinline__ void mma_tf32(float* c, const unsigned* a, const unsigned* b) {
    asm volatile(
        "mma.sync.aligned.m16n8k8.row.col.f32.tf32.tf32.f32 "
        "{%0,%1,%2,%3}, {%4,%5,%6,%7}, {%8,%9}, {%0,%1,%2,%3};"
        : "+f"(c[0]), "+f"(c[1]), "+f"(c[2]), "+f"(c[3])
        : "r"(a[0]), "r"(a[1]), "r"(a[2]), "r"(a[3]), "r"(b[0]), "r"(b[1]));
}

// ---------------------------------------------------------------------------
// K1: per (b, q-strip 128): loop 32 k-tiles of 64.
//   QK tf32 mma -> p = exp(scale*e + log(mask+1e-6)) -> write unnormalized p
//   to attT[b][k][q]; block-local row sums -> g_inv.
// 256 threads = 8 warps, warp grid 2(m=k) x 4(n=q), warp tile 32x32.
// smem: Qs[128][136] + Ks[128][72] + sred[256] = 107,520 B -> 2 CTAs/SM.
// ---------------------------------------------------------------------------
__global__ void __launch_bounds__(256, 2)
qk_exp_kernel(const float* __restrict__ Q, const float* __restrict__ Kg,
              const float* __restrict__ mask, float* __restrict__ attT) {
    extern __shared__ float sm[];
    float* Qs   = sm;               // [128 c][136]  tf32 Q tile (persistent)
    float* Ks   = sm + 17408;       // [128 c][72]   tf32 K tile
    float* sred = sm + 26624;       // [256]

    const int b   = blockIdx.y;
    const int q0  = blockIdx.x * 128;
    const int tid = threadIdx.x;
    const int warp = tid >> 5, lane = tid & 31;
    const int wm = warp >> 2, wn = warp & 3;    // 2(m) x 4(n)
    const int g = lane >> 2, tg = lane & 3;

    const float* Qb   = Q  + (size_t)b * Cn * Ln;
    const float* Kb   = Kg + (size_t)b * Cn * Ln;
    const float* mrow = mask + b * Ln;
    float* Tb = attT + (size_t)b * Ln * Ln;

    sred[tid] = 0.f;

    // stage Q tile [c=128][q=128], tf32-rounded
#pragma unroll
    for (int i = 0; i < 16; i++) {
        int id = tid + i * 256;
        int r = id >> 5, c4 = (id & 31) << 2;
        float4 v = *reinterpret_cast<const float4*>(Qb + (size_t)r * Ln + q0 + c4);
        unsigned* d = reinterpret_cast<unsigned*>(Qs + r * 136 + c4);
        d[0] = f2tf32(v.x); d[1] = f2tf32(v.y); d[2] = f2tf32(v.z); d[3] = f2tf32(v.w);
    }

    // prefetch K tile 0 ([c=128][k=64])
    float4 pf[8];
#pragma unroll
    for (int i = 0; i < 8; i++) {
        int id = tid + i * 256;
        pf[i] = *reinterpret_cast<const float4*>(Kb + (size_t)(id >> 4) * Ln + ((id & 15) << 2));
    }
    __syncthreads();

    const float scale = 0.08838834764831845f;   // 1/sqrt(128)

    for (int kt = 0; kt < 32; kt++) {
        const int k0 = kt * 64;

        // commit prefetched K tile (convert to tf32)
#pragma unroll
        for (int i = 0; i < 8; i++) {
            int id = tid + i * 256;
            unsigned* d = reinterpret_cast<unsigned*>(Ks + (id >> 4) * 72 + ((id & 15) << 2));
            d[0] = f2tf32(pf[i].x); d[1] = f2tf32(pf[i].y);
            d[2] = f2tf32(pf[i].z); d[3] = f2tf32(pf[i].w);
        }
        __syncthreads();

        // prefetch next K tile (overlaps mma)
        {
            int kn = ((kt + 1) & 31) * 64;
#pragma unroll
            for (int i = 0; i < 8; i++) {
                int id = tid + i * 256;
                pf[i] = *reinterpret_cast<const float4*>(
                    Kb + (size_t)(id >> 4) * Ln + kn + ((id & 15) << 2));
            }
        }

        // QK mma: acc[m=k 32][n=q 32]
        float acc[2][4][4];
#pragma unroll
        for (int i = 0; i < 2; i++)
#pragma unroll
            for (int j = 0; j < 4; j++)
#pragma unroll
                for (int v = 0; v < 4; v++) acc[i][j][v] = 0.f;

#pragma unroll
        for (int cc = 0; cc < Cn; cc += 8) {
            unsigned a[2][4];
#pragma unroll
            for (int mt = 0; mt < 2; mt++) {
                int m = wm * 32 + mt * 16 + g;
                a[mt][0] = __float_as_uint(Ks[(cc + tg) * 72 + m]);
                a[mt][1] = __float_as_uint(Ks[(cc + tg) * 72 + m + 8]);
                a[mt][2] = __float_as_uint(Ks[(cc + tg + 4) * 72 + m]);
                a[mt][3] = __float_as_uint(Ks[(cc + tg + 4) * 72 + m + 8]);
            }
#pragma unroll
            for (int nt = 0; nt < 4; nt++) {
                int n = wn * 32 + nt * 8 + g;
                unsigned bb[2];
                bb[0] = __float_as_uint(Qs[(cc + tg) * 136 + n]);
                bb[1] = __float_as_uint(Qs[(cc + tg + 4) * 136 + n]);
                mma_tf32(acc[0][nt], a[0], bb);
                mma_tf32(acc[1][nt], a[1], bb);
            }
        }

        // epilogue: exp, streaming store, row-sum accumulation
        float sp[8];
#pragma unroll
        for (int j = 0; j < 8; j++) sp[j] = 0.f;
#pragma unroll
        for (int mt = 0; mt < 2; mt++) {
            int kgl = k0 + wm * 32 + mt * 16 + g;
            float l0 = __logf(__ldg(mrow + kgl) + 1e-6f);
            float l1 = __logf(__ldg(mrow + kgl + 8) + 1e-6f);
            float* row0 = Tb + (size_t)kgl * Ln + q0 + wn * 32;
            float* row1 = row0 + (size_t)8 * Ln;
#pragma unroll
            for (int nt = 0; nt < 4; nt++) {
                int qoff = nt * 8 + 2 * tg;
                float p0 = __expf(fmaf(acc[mt][nt][0], scale, l0));
                float p1 = __expf(fmaf(acc[mt][nt][1], scale, l0));
                float p2 = __expf(fmaf(acc[mt][nt][2], scale, l1));
                float p3 = __expf(fmaf(acc[mt][nt][3], scale, l1));
                sp[nt * 2]     += p0 + p2;
                sp[nt * 2 + 1] += p1 + p3;
                __stcs(reinterpret_cast<float2*>(row0 + qoff), make_float2(p0, p1));
                __stcs(reinterpret_cast<float2*>(row1 + qoff), make_float2(p2, p3));
            }
        }
#pragma unroll
        for (int j = 0; j < 8; j++) {
            float v = sp[j];
            v += __shfl_xor_sync(0xffffffffu, v, 4);
            v += __shfl_xor_sync(0xffffffffu, v, 8);
            v += __shfl_xor_sync(0xffffffffu, v, 16);
            if (g == 0)
                sred[wm * 128 + wn * 32 + (j >> 1) * 8 + 2 * tg + (j & 1)] += v;
        }
        __syncthreads();
    }

    if (tid < 128)
        g_inv[b * Ln + q0 + tid] = 1.0f / (sred[tid] + sred[128 + tid]);
}

// ---------------------------------------------------------------------------
// K2: per (b, q-strip 128): loop 64 k-tiles of 32.
//   read unnormalized p, scale by inv[q]*mask[k], write final attT,
//   AND accumulate out[c][q] += V * p_norm via tf32 mma.
// V tiles double-buffered with cp.async (raw fp32, tf32-rounded at frag load).
// 256 threads = 8 warps, warp grid 4(m=c) x 2(n=q), warp tile 32x64.
// smem: Ps[32][136] + Vs[2][128][36] + mrow[2048] + sinv[128] = 62,976 B.
// ---------------------------------------------------------------------------
__global__ void __launch_bounds__(256, 2)
norm_av_kernel(const float* __restrict__ V, const float* __restrict__ mask,
               float* __restrict__ attT, float* __restrict__ out) {
    extern __shared__ float sm2[];
    float* Ps   = sm2;              // [32 k][136]  tf32 normalized p tile
    float* Vs   = sm2 + 4352;       // [2][128 c][36] raw V tiles
    float* mrow = sm2 + 13568;      // [2048]
    float* sinv = sm2 + 15616;      // [128]

    const int b   = blockIdx.y;
    const int q0  = blockIdx.x * 128;
    const int tid = threadIdx.x;
    const int warp = tid >> 5, lane = tid & 31;
    const int wm = warp >> 1, wn = warp & 1;    // 4(m) x 2(n)
    const int g = lane >> 2, tg = lane & 3;

    const float* Vb = V + (size_t)b * Cn * Ln;
    float* Tb = attT + (size_t)b * Ln * Ln;

#pragma unroll
    for (int i = 0; i < 8; i++) mrow[tid + i * 256] = mask[b * Ln + tid + i * 256];
    if (tid < 128) sinv[tid] = g_inv[b * Ln + q0 + tid];

    // cp.async V tile 0 into buffer 0
#pragma unroll
    for (int i = 0; i < 4; i++) {
        int id = tid + i * 256;
        int r = id >> 3, ch = (id & 7) << 2;
        unsigned dst = (unsigned)__cvta_generic_to_shared(Vs + r * 36 + ch);
        asm volatile("cp.async.cg.shared.global [%0], [%1], 16;"
                     :: "r"(dst), "l"(Vb + (size_t)r * Ln + ch));
    }
    asm volatile("cp.async.commit_group;");
    __syncthreads();

    float oacc[2][8][4];
#pragma unroll
    for (int i = 0; i < 2; i++)
#pragma unroll
        for (int j = 0; j < 8; j++)
#pragma unroll
            for (int v = 0; v < 4; v++) oacc[i][j][v] = 0.f;

    for (int kt = 0; kt < 64; kt++) {
        const int k0 = kt * 32;

        // issue cp.async for V tile kt+1 (other buffer)
        {
            int kn = ((kt + 1) & 63) * 32;
            float* vdst = Vs + ((kt + 1) & 1) * 4608;
#pragma unroll
            for (int i = 0; i < 4; i++) {
                int id = tid + i * 256;
                int r = id >> 3, ch = (id & 7) << 2;
                unsigned dst = (unsigned)__cvta_generic_to_shared(vdst + r * 36 + ch);
                asm volatile("cp.async.cg.shared.global [%0], [%1], 16;"
                             :: "r"(dst), "l"(Vb + (size_t)r * Ln + kn + ch));
            }
            asm volatile("cp.async.commit_group;");
        }

        // p tile: load, normalize+mask, write final attT, stash tf32 in Ps
#pragma unroll
        for (int i = 0; i < 4; i++) {
            int id = tid + i * 256;
            int r = id >> 5, c4 = (id & 31) << 2;
            int kgl = k0 + r;
            float mk = mrow[kgl];
            float* gp = Tb + (size_t)kgl * Ln + q0 + c4;
            float4 v = __ldcs(reinterpret_cast<const float4*>(gp));
            float4 iv = *reinterpret_cast<const float4*>(sinv + c4);
            v.x *= iv.x * mk; v.y *= iv.y * mk;
            v.z *= iv.z * mk; v.w *= iv.w * mk;
            __stcs(reinterpret_cast<float4*>(gp), v);
            unsigned* d = reinterpret_cast<unsigned*>(Ps + r * 136 + c4);
            d[0] = f2tf32(v.x); d[1] = f2tf32(v.y);
            d[2] = f2tf32(v.z); d[3] = f2tf32(v.w);
        }
        asm volatile("cp.async.wait_group 1;");
        __syncthreads();

        // AV mma: oacc[m=c 32][n=q 64] += V * Pnorm
        const float* Vt = Vs + (kt & 1) * 4608;
#pragma unroll
        for (int kk = 0; kk < 32; kk += 8) {
            unsigned a[2][4];
#pragma unroll
            for (int mt = 0; mt < 2; mt++) {
                int m = wm * 32 + mt * 16 + g;
                a[mt][0] = f2tf32(Vt[m * 36 + kk + tg]);
                a[mt][1] = f2tf32(Vt[(m + 8) * 36 + kk + tg]);
                a[mt][2] = f2tf32(Vt[m * 36 + kk + tg + 4]);
                a[mt][3] = f2tf32(Vt[(m + 8) * 36 + kk + tg + 4]);
            }
#pragma unroll
            for (int nt = 0; nt < 8; nt++) {
                int n = wn * 64 + nt * 8 + g;
                unsigned bb[2];
                bb[0] = __float_as_uint(Ps[(kk + tg) * 136 + n]);
                bb[1] = __float_as_uint(Ps[(kk + tg + 4) * 136 + n]);
                mma_tf32(oacc[0][nt], a[0], bb);
                mma_tf32(oacc[1][nt], a[1], bb);
            }
        }
        __syncthreads();
    }

    // out[b][c][q] (already normalized & masked)
    float* ob = out + (size_t)b * Cn * Ln;
#pragma unroll
    for (int mt = 0; mt < 2; mt++) {
        int c = wm * 32 + mt * 16 + g;
#pragma unroll
        for (int nt = 0; nt < 8; nt++) {
            int q = q0 + wn * 64 + nt * 8 + 2 * tg;
            __stcs(reinterpret_cast<float2*>(ob + (size_t)c * Ln + q),
                   make_float2(oacc[mt][nt][0], oacc[mt][nt][1]));
            __stcs(reinterpret_cast<float2*>(ob + (size_t)(c + 8) * Ln + q),
                   make_float2(oacc[mt][nt][2], oacc[mt][nt][3]));
        }
    }
}

// ---------------------------------------------------------------------------
extern "C" void kernel_launch(void* const* d_in, const int* in_sizes, int n_in,
                              void* d_out, int out_size) {
    const float* Q    = (const float*)d_in[0];
    const float* K    = (const float*)d_in[1];
    const float* V    = (const float*)d_in[2];
    const float* mask = (const float*)d_in[3];

    float* out  = (float*)d_out;                  // [B, C, L]
    float* attT = out + (size_t)Bn * Cn * Ln;     // [B, Lk, Lq]

    const int SMEM1 = 26880 * 4;                  // 107,520 B
    const int SMEM2 = 15744 * 4;                  //  62,976 B
    cudaFuncSetAttribute(qk_exp_kernel,
                         cudaFuncAttributeMaxDynamicSharedMemorySize, SMEM1);
    cudaFuncSetAttribute(norm_av_kernel,
                         cudaFuncAttributeMaxDynamicSharedMemorySize, SMEM2);

    dim3 grid(Ln / 128, Bn);                      // (16, 16) = 256 blocks
    qk_exp_kernel<<<grid, 256, SMEM1>>>(Q, K, mask, attT);
    norm_av_kernel<<<grid, 256, SMEM2>>>(V, mask, attT, out);
}